// round 1
// baseline (speedup 1.0000x reference)
#include <cuda_runtime.h>
#include <math.h>

// learned mask M (8x8) and DCT basis C (8x8), produced by prep_kernel
static __device__ float g_C[64];
static __device__ float g_M[64];

__global__ void prep_kernel(const float* __restrict__ noise,
                            const float* __restrict__ qmat,
                            const float* __restrict__ qmw,
                            const float* __restrict__ w1, const float* __restrict__ b1,
                            const float* __restrict__ w2, const float* __restrict__ b2,
                            const float* __restrict__ w3, const float* __restrict__ b3)
{
    __shared__ float coef[16];
    int t = threadIdx.x;  // 64 threads

    // DCT matrix (double precision, truncated pi exactly as reference)
    if (t < 64) {
        int i = t >> 3, j = t & 7;
        const double PI = 3.1415926;
        double v;
        if (i == 0) v = sqrt(1.0 / 8.0);
        else        v = cos(PI * (double)i * (double)(2 * j + 1) / 16.0) * sqrt(2.0 / 8.0);
        g_C[t] = (float)v;
    }

    if (t == 0) {
        float nl = noise[0];
        float h1[16], h2[16], nr[18];
        const float inv_sqrt2 = 0.7071067811865476f;
        #pragma unroll
        for (int j = 0; j < 16; j++) {
            float z = fmaf(nl, w1[j], b1[j]);
            h1[j] = 0.5f * z * (1.0f + erff(z * inv_sqrt2));   // exact GELU
        }
        #pragma unroll
        for (int j = 0; j < 16; j++) {
            float z = b2[j];
            #pragma unroll
            for (int k = 0; k < 16; k++) z = fmaf(h1[k], w2[k * 16 + j], z);
            h2[j] = 0.5f * z * (1.0f + erff(z * inv_sqrt2));
        }
        #pragma unroll
        for (int j = 0; j < 18; j++) {
            float z = b3[j];
            #pragma unroll
            for (int k = 0; k < 16; k++) z = fmaf(h2[k], w3[k * 18 + j], z);
            nr[j] = z;
        }
        // softmax(qmat_weights)
        float mx = qmw[0];
        #pragma unroll
        for (int i = 1; i < 16; i++) mx = fmaxf(mx, qmw[i]);
        float e[16], sum = 0.f;
        #pragma unroll
        for (int i = 0; i < 16; i++) { e[i] = expf(qmw[i] - mx); sum += e[i]; }
        float inv = 1.0f / sum;
        #pragma unroll
        for (int i = 0; i < 16; i++) {
            float qw = e[i] * inv * nr[0] + nr[1];
            coef[i] = qw * nr[2 + i];
        }
    }
    __syncthreads();

    if (t < 64) {
        float s = 0.f;
        #pragma unroll
        for (int i = 0; i < 16; i++) s = fmaf(coef[i], qmat[i * 64 + t], s);
        g_M[t] = s;
    }
}

// One thread per 8x8 block. low = C^T((C X C^T) .* M) C ; high = X - low.
__global__ __launch_bounds__(128) void dct_main(const float* __restrict__ x,
                                                float* __restrict__ lo,
                                                float* __restrict__ hi)
{
    __shared__ float Cs[64];
    __shared__ float Ms[64];
    int tid = threadIdx.x;
    if (tid < 64) { Cs[tid] = g_C[tid]; Ms[tid] = g_M[tid]; }
    __syncthreads();

    int g   = blockIdx.x * 128 + tid;        // global 8x8-block id, < 524288
    int img = g >> 6;                        // image id (B*Ch)
    int blk = g & 63;                        // block within 64x64 image
    int off = (img << 12) + ((blk >> 3) << 9) + ((blk & 7) << 3);

    const float* xp = x + off;
    float X[64];
    #pragma unroll
    for (int r = 0; r < 8; r++) {
        float4 a = *reinterpret_cast<const float4*>(xp + (r << 6));
        float4 b = *reinterpret_cast<const float4*>(xp + (r << 6) + 4);
        X[r * 8 + 0] = a.x; X[r * 8 + 1] = a.y; X[r * 8 + 2] = a.z; X[r * 8 + 3] = a.w;
        X[r * 8 + 4] = b.x; X[r * 8 + 5] = b.y; X[r * 8 + 6] = b.z; X[r * 8 + 7] = b.w;
    }

    // Y = (C X C^T) .* M
    float Y[64];
    #pragma unroll
    for (int i = 0; i < 8; i++) {
        float t[8];
        #pragma unroll
        for (int k = 0; k < 8; k++) {
            float s = Cs[i * 8 + 0] * X[k];
            #pragma unroll
            for (int j = 1; j < 8; j++) s = fmaf(Cs[i * 8 + j], X[j * 8 + k], s);
            t[k] = s;
        }
        #pragma unroll
        for (int m = 0; m < 8; m++) {
            float s = t[0] * Cs[m * 8 + 0];
            #pragma unroll
            for (int k = 1; k < 8; k++) s = fmaf(t[k], Cs[m * 8 + k], s);
            Y[i * 8 + m] = s * Ms[i * 8 + m];
        }
    }

    // low = C^T Y C, streamed row-by-row; high = X - low
    float* lp = lo + off;
    float* hp = hi + off;
    #pragma unroll
    for (int i = 0; i < 8; i++) {
        float t[8];
        #pragma unroll
        for (int k = 0; k < 8; k++) {
            float s = Cs[i] * Y[k];                       // C[0][i] * Y[0][k]
            #pragma unroll
            for (int j = 1; j < 8; j++) s = fmaf(Cs[j * 8 + i], Y[j * 8 + k], s);
            t[k] = s;
        }
        float l[8];
        #pragma unroll
        for (int m = 0; m < 8; m++) {
            float s = t[0] * Cs[m];                       // * C[0][m]
            #pragma unroll
            for (int k = 1; k < 8; k++) s = fmaf(t[k], Cs[k * 8 + m], s);
            l[m] = s;
        }
        *reinterpret_cast<float4*>(lp + (i << 6))     = make_float4(l[0], l[1], l[2], l[3]);
        *reinterpret_cast<float4*>(lp + (i << 6) + 4) = make_float4(l[4], l[5], l[6], l[7]);
        *reinterpret_cast<float4*>(hp + (i << 6)) =
            make_float4(X[i * 8 + 0] - l[0], X[i * 8 + 1] - l[1],
                        X[i * 8 + 2] - l[2], X[i * 8 + 3] - l[3]);
        *reinterpret_cast<float4*>(hp + (i << 6) + 4) =
            make_float4(X[i * 8 + 4] - l[4], X[i * 8 + 5] - l[5],
                        X[i * 8 + 6] - l[6], X[i * 8 + 7] - l[7]);
    }
}

extern "C" void kernel_launch(void* const* d_in, const int* in_sizes, int n_in,
                              void* d_out, int out_size)
{
    const float* x     = (const float*)d_in[0];
    const float* noise = (const float*)d_in[1];
    const float* qmat  = (const float*)d_in[2];
    const float* qmw   = (const float*)d_in[3];
    const float* w1    = (const float*)d_in[4];
    const float* b1    = (const float*)d_in[5];
    const float* w2    = (const float*)d_in[6];
    const float* b2    = (const float*)d_in[7];
    const float* w3    = (const float*)d_in[8];
    const float* b3    = (const float*)d_in[9];

    float* out = (float*)d_out;
    int N = out_size / 2;                 // elements per output tensor (33554432)
    float* lo = out;
    float* hi = out + N;

    prep_kernel<<<1, 64>>>(noise, qmat, qmw, w1, b1, w2, b2, w3, b3);

    int nblocks8x8 = N / 64;              // 524288 threads, one per 8x8 block
    dct_main<<<nblocks8x8 / 128, 128>>>(x, lo, hi);
}